// round 15
// baseline (speedup 1.0000x reference)
#include <cuda_runtime.h>
#include <math.h>
#include <cstdint>

#define Bsz 4
#define Lsz 256
#define Hsz 768
#define NL  13

typedef unsigned long long u64;

// ---------------------------------------------------------------------------
// f32x2 packed helpers
// ---------------------------------------------------------------------------
__device__ __forceinline__ u64 pack2(float lo, float hi) {
    u64 r; asm("mov.b64 %0,{%1,%2};" : "=l"(r) : "f"(lo), "f"(hi)); return r;
}
__device__ __forceinline__ u64 bcast2(float x) { return pack2(x, x); }
__device__ __forceinline__ void unpack2(u64 v, float& lo, float& hi) {
    asm("mov.b64 {%0,%1},%2;" : "=f"(lo), "=f"(hi) : "l"(v));
}
__device__ __forceinline__ u64 fadd2_(u64 a, u64 b) {
    u64 d; asm("add.rn.f32x2 %0,%1,%2;" : "=l"(d) : "l"(a), "l"(b)); return d;
}
__device__ __forceinline__ u64 fmul2_(u64 a, u64 b) {
    u64 d; asm("mul.rn.f32x2 %0,%1,%2;" : "=l"(d) : "l"(a), "l"(b)); return d;
}
__device__ __forceinline__ u64 ffma2_(u64 a, u64 b, u64 c) {
    u64 d; asm("fma.rn.f32x2 %0,%1,%2,%3;" : "=l"(d) : "l"(a), "l"(b), "l"(c)); return d;
}

// tf32 truncation mask + packed round-to-nearest increment
#define TF32_MASK2 0xFFFFE000FFFFE000ULL
#define TF32_MASK1 0xFFFFE000u
#define TF32_RND2  0x0000100000001000ULL
#define TF32_RND1  0x00001000u

// warp mma m16n8k8 tf32, D += A*B (row.col)
__device__ __forceinline__ void mma8(float* d, const uint32_t* a, uint32_t b0, uint32_t b1) {
    asm volatile(
        "mma.sync.aligned.m16n8k8.row.col.f32.tf32.tf32.f32 "
        "{%0,%1,%2,%3}, {%4,%5,%6,%7}, {%8,%9}, {%0,%1,%2,%3};"
        : "+f"(d[0]), "+f"(d[1]), "+f"(d[2]), "+f"(d[3])
        : "r"(a[0]), "r"(a[1]), "r"(a[2]), "r"(a[3]), "r"(b0), "r"(b1));
}

// ---------------------------------------------------------------------------
// Compile-time Chebyshev fit of S(u) = 0.5*sqrt(u)*erf(sqrt(u/2)), u in
// [0,UMAX]; gelu(h) = 0.5h + S(h^2). Evaluated Estrin-style in w = h^2-UMAX/2.
// ---------------------------------------------------------------------------
namespace fitns {
constexpr double PI_ = 3.14159265358979323846;
constexpr int    NC  = 10;
constexpr double UMAX = 14.0;

constexpr double cerf(double x) {
    double t = x, s = x;
    for (int n = 1; n < 80; n++) { t = t * (-(x * x) / n); s = s + t / (2.0 * n + 1.0); }
    return s * 1.12837916709551257390;
}
constexpr double ccos(double x) {
    double t = 1.0, s = 1.0;
    for (int n = 1; n < 40; n++) { t = t * (-(x * x) / ((2.0 * n - 1.0) * (2.0 * n))); s = s + t; }
    return s;
}
constexpr double csqrt(double x) {
    double r = (x > 1.0) ? x : 1.0;
    for (int i = 0; i < 100; i++) r = 0.5 * (r + x / r);
    return r;
}
struct Fit { double c[NC]; };
constexpr Fit mkfit() {
    Fit F{};
    double fv[NC] = {}, cth[NC] = {};
    for (int m = 0; m < NC; m++) {
        double th = PI_ * (m + 0.5) / NC;
        double v = ccos(th);
        cth[m] = v;
        double u = 0.5 * UMAX * (1.0 + v);
        double su = csqrt(u);
        fv[m] = 0.5 * su * cerf(su * 0.70710678118654752440);
    }
    double a[NC] = {};
    for (int k = 0; k < NC; k++) {
        double s = 0.0;
        for (int m = 0; m < NC; m++) {
            double c0 = 1.0, c1 = cth[m], ck = 1.0;
            if (k == 1) ck = c1;
            else if (k >= 2) {
                for (int i = 2; i <= k; i++) { ck = 2.0 * cth[m] * c1 - c0; c0 = c1; c1 = ck; }
            }
            s += fv[m] * ck;
        }
        a[k] = 2.0 * s / NC;
    }
    a[0] *= 0.5;
    double T0[NC] = {}, T1[NC] = {}, Tn[NC] = {};
    T0[0] = 1.0; T1[1] = 1.0;
    F.c[0] += a[0]; F.c[1] += a[1];
    for (int k = 2; k < NC; k++) {
        for (int j = 0; j < NC; j++) { double tp = (j > 0) ? T1[j - 1] : 0.0; Tn[j] = 2.0 * tp - T0[j]; }
        for (int j = 0; j <= k; j++) F.c[j] += a[k] * Tn[j];
        for (int j = 0; j < NC; j++) { T0[j] = T1[j]; T1[j] = Tn[j]; }
    }
    double sc = 1.0;
    for (int j = 0; j < NC; j++) { F.c[j] /= sc; sc *= (UMAX * 0.5); }
    return F;
}
constexpr Fit FIT = mkfit();
}  // namespace fitns

__constant__ float d_coef[fitns::NC] = {
    (float)fitns::FIT.c[0], (float)fitns::FIT.c[1], (float)fitns::FIT.c[2],
    (float)fitns::FIT.c[3], (float)fitns::FIT.c[4], (float)fitns::FIT.c[5],
    (float)fitns::FIT.c[6], (float)fitns::FIT.c[7], (float)fitns::FIT.c[8],
    (float)fitns::FIT.c[9]
};

__device__ float g_xs[Bsz * Lsz * Hsz];   // xs_proj + b1
__device__ float g_xe[Bsz * Lsz * Hsz];   // xe_proj

// Estrin gelu: depth ~7 fma stages instead of 11
__device__ __forceinline__ u64 gelu2(u64 h, const u64* c, u64 wsh, u64 hf) {
    u64 w  = ffma2_(h, h, wsh);
    u64 w2 = fmul2_(w, w);
    u64 p01 = ffma2_(c[1], w, c[0]);
    u64 p23 = ffma2_(c[3], w, c[2]);
    u64 p45 = ffma2_(c[5], w, c[4]);
    u64 p67 = ffma2_(c[7], w, c[6]);
    u64 p89 = ffma2_(c[9], w, c[8]);
    u64 w4 = fmul2_(w2, w2);
    u64 q0 = ffma2_(p23, w2, p01);
    u64 q1 = ffma2_(p67, w2, p45);
    u64 r1 = ffma2_(p89, w4, q1);
    u64 P  = ffma2_(r1, w4, q0);
    return ffma2_(h, hf, P);
}

// ---------------------------------------------------------------------------
// Kernel 1: projection GEMM on tensor pipe (mma.sync tf32).
//   xs[m,n] = sum_h X[m,h] * W1[h,n]  — W1 rows are the CONTRACTION dim.
//   A = X rounded-to-tf32 (unbiased); B = W1 exact hi/lo split, staged
//   TRANSPOSED from W1[h][n] into Bh/Bl[n][perm(h)].
//   Block 64x64, 8 warps (m16 x n32 each), K chunk 32, stride-40 smem.
// ---------------------------------------------------------------------------
#define PKC  32
#define PSTR 40

__global__ __launch_bounds__(256) void proj_kernel(
    const float* __restrict__ X, const float* __restrict__ W1,
    const float* __restrict__ b1)
{
    __shared__ float Ah[64 * PSTR];
    __shared__ float Bh[64 * PSTR];
    __shared__ float Bl[64 * PSTR];

    const int m0  = blockIdx.y * 64;
    const int n0g = blockIdx.x * 64;
    const int half = (n0g >= Hsz) ? 1 : 0;
    const int n0  = n0g - half * Hsz;
    const float* Bbase = W1 + (size_t)half * Hsz * Hsz;   // (768 h x 768 n)
    float* Out = half ? g_xe : g_xs;

    const int tid = threadIdx.x;
    const int w   = tid >> 5;
    const int t   = tid & 31;
    const int g   = t >> 2;          // 0..7
    const int tig = t & 3;           // 0..3
    const int mrow  = (w & 3) * 16;  // warp's m offset in tile
    const int nhalf = (w >> 2) * 32; // warp's n offset in tile

    float acc[4][4];                 // 4 n-tiles of n8
#pragma unroll
    for (int nt = 0; nt < 4; nt++)
#pragma unroll
        for (int q = 0; q < 4; q++) acc[nt][q] = 0.f;

    for (int kc = 0; kc < Hsz; kc += PKC) {
        __syncthreads();
        // stage A (64 rows x 32 k), rounded to tf32, pair-permuted
#pragma unroll
        for (int e = tid; e < 512; e += 256) {
            int row = e >> 3, c4 = (e & 7) * 4;
            float4 v = *(const float4*)(X + (size_t)(m0 + row) * Hsz + kc + c4);
            int q8 = c4 & ~7, sh = (c4 & 4) ? 1 : 0;
            float* dst = &Ah[row * PSTR + q8 + sh];
            dst[0] = __uint_as_float((__float_as_uint(v.x) + TF32_RND1) & TF32_MASK1);
            dst[2] = __uint_as_float((__float_as_uint(v.y) + TF32_RND1) & TF32_MASK1);
            dst[4] = __uint_as_float((__float_as_uint(v.z) + TF32_RND1) & TF32_MASK1);
            dst[6] = __uint_as_float((__float_as_uint(v.w) + TF32_RND1) & TF32_MASK1);
        }
        // stage B: read W1[kc+kk][n0+n] (n fast => coalesced), transpose into
        // Bh/Bl[n][perm(kk)] with exact hi/lo split
#pragma unroll
        for (int e = tid; e < PKC * 64; e += 256) {
            int kk = e >> 6, n = e & 63;
            float v = Bbase[(size_t)(kc + kk) * Hsz + n0 + n];
            float hv = __uint_as_float(__float_as_uint(v) & TF32_MASK1);
            int pp = (kk & ~7) + ((kk & 3) << 1) + ((kk & 7) >> 2);
            Bh[n * PSTR + pp] = hv;
            Bl[n * PSTR + pp] = v - hv;
        }
        __syncthreads();

#pragma unroll
        for (int q = 0; q < 4; q++) {
            const int base = q * 8 + tig * 2;
            float2 ag  = *(const float2*)&Ah[(mrow + g) * PSTR + base];
            float2 ag8 = *(const float2*)&Ah[(mrow + g + 8) * PSTR + base];
            uint32_t au[4] = {__float_as_uint(ag.x),  __float_as_uint(ag8.x),
                              __float_as_uint(ag.y),  __float_as_uint(ag8.y)};
#pragma unroll
            for (int nt = 0; nt < 4; nt++) {
                const int n = nhalf + nt * 8 + g;
                float2 bh = *(const float2*)&Bh[n * PSTR + base];
                float2 bl = *(const float2*)&Bl[n * PSTR + base];
                mma8(acc[nt], au, __float_as_uint(bh.x), __float_as_uint(bh.y));
                mma8(acc[nt], au, __float_as_uint(bl.x), __float_as_uint(bl.y));
            }
        }
    }

    // epilogue: c0=C[g][2tig], c1=C[g][2tig+1], c2/c3 row g+8
    const int row0 = m0 + mrow + g;
    const int row1 = row0 + 8;
#pragma unroll
    for (int nt = 0; nt < 4; nt++) {
        const int n = n0 + nhalf + nt * 8 + 2 * tig;
        float bias0 = half ? 0.f : b1[n];
        float bias1 = half ? 0.f : b1[n + 1];
        Out[(size_t)row0 * Hsz + n]     = acc[nt][0] + bias0;
        Out[(size_t)row0 * Hsz + n + 1] = acc[nt][1] + bias1;
        Out[(size_t)row1 * Hsz + n]     = acc[nt][2] + bias0;
        Out[(size_t)row1 * Hsz + n + 1] = acc[nt][3] + bias1;
    }
}

// ---------------------------------------------------------------------------
// Kernel 2: span scorer — Estrin gelu in f32x2, contraction via mma.sync tf32.
//   A = round-to-nearest tf32 of gelu output (packed int add + mask);
//   B = W2 exact hi/lo (staged). 8 mma per q-step.
// ---------------------------------------------------------------------------
#define CK   64
#define CSTR 72

__global__ __launch_bounds__(256, 2) void span_kernel(
    const float* __restrict__ W2, const float* __restrict__ b2,
    float* __restrict__ out)
{
    __shared__ float xsp[16 * CSTR];
    __shared__ float xep[16 * CSTR];
    __shared__ float w2h[16 * CSTR];
    __shared__ float w2l[16 * CSTR];

    const int tid = threadIdx.x;
    const int w   = tid >> 5;
    const int t   = tid & 31;
    const int g   = t >> 2;     // 0..7
    const int tig = t & 3;      // 0..3
    const int b  = blockIdx.z;
    const int i0 = blockIdx.y * 16;
    const int j0 = blockIdx.x * 16;

    u64 c[fitns::NC];
#pragma unroll
    for (int k = 0; k < fitns::NC; k++) c[k] = bcast2(d_coef[k]);
    const u64 wsh = bcast2((float)(-fitns::UMAX * 0.5));
    const u64 hf  = bcast2(0.5f);

    float acc[2][2][4];   // [mtile][ntile][frag]
#pragma unroll
    for (int a = 0; a < 2; a++)
#pragma unroll
        for (int nn = 0; nn < 2; nn++)
#pragma unroll
            for (int q = 0; q < 4; q++) acc[a][nn][q] = 0.f;

    for (int kc = 0; kc < Hsz; kc += CK) {
        __syncthreads();
        // ---- stage W2 chunk transposed: [n(16, zero-pad)][perm(k)], hi+lo
#pragma unroll
        for (int e = tid; e < CK * 16; e += 256) {
            int k = e >> 4, n = e & 15;
            float v = (n < NL) ? W2[(size_t)(kc + k) * NL + n] : 0.f;
            float hvf = __uint_as_float(__float_as_uint(v) & TF32_MASK1);
            int pp = (k & ~7) + ((k & 3) << 1) + ((k & 7) >> 2);
            w2h[n * CSTR + pp] = hvf;
            w2l[n * CSTR + pp] = v - hvf;
        }
        // ---- stage xs / xe chunk with pair-permuted in-chunk layout
        {
            int rr = tid >> 4, c4 = (tid & 15) * 4;
            int q8 = c4 & ~7, sh = (c4 & 4) ? 1 : 0;
            float4 v = *(const float4*)(g_xs + (size_t)(b * Lsz + i0 + rr) * Hsz + kc + c4);
            xsp[rr * CSTR + q8 + sh + 0] = v.x;
            xsp[rr * CSTR + q8 + sh + 2] = v.y;
            xsp[rr * CSTR + q8 + sh + 4] = v.z;
            xsp[rr * CSTR + q8 + sh + 6] = v.w;
            float4 ve = *(const float4*)(g_xe + (size_t)(b * Lsz + j0 + rr) * Hsz + kc + c4);
            xep[rr * CSTR + q8 + sh + 0] = ve.x;
            xep[rr * CSTR + q8 + sh + 2] = ve.y;
            xep[rr * CSTR + q8 + sh + 4] = ve.z;
            xep[rr * CSTR + q8 + sh + 6] = ve.w;
        }
        __syncthreads();

#pragma unroll 2
        for (int q = 0; q < CK / 8; q++) {
            const int base = q * 8 + tig * 2;
            // B fragments (float2 = {k=tig, k=tig+4})
            float2 bh0 = *(const float2*)&w2h[g * CSTR + base];
            float2 bh1 = *(const float2*)&w2h[(g + 8) * CSTR + base];
            float2 bl0 = *(const float2*)&w2l[g * CSTR + base];
            float2 bl1 = *(const float2*)&w2l[(g + 8) * CSTR + base];
            const uint32_t bh0x = __float_as_uint(bh0.x), bh0y = __float_as_uint(bh0.y);
            const uint32_t bh1x = __float_as_uint(bh1.x), bh1y = __float_as_uint(bh1.y);
            const uint32_t bl0x = __float_as_uint(bl0.x), bl0y = __float_as_uint(bl0.y);
            const uint32_t bl1x = __float_as_uint(bl1.x), bl1y = __float_as_uint(bl1.y);
            // xe rows j=g and j=g+8 (shared by both m-tiles)
            u64 xeg  = *(const u64*)&xep[g * CSTR + base];
            u64 xeg8 = *(const u64*)&xep[(g + 8) * CSTR + base];
#pragma unroll
            for (int mt = 0; mt < 2; mt++) {
                const int iw = 2 * w + mt;
                u64 xs2 = *(const u64*)&xsp[iw * CSTR + base];
                u64 g02 = gelu2(fadd2_(xs2, xeg),  c, wsh, hf);   // row j=g,   cols {tig,tig+4}
                u64 g13 = gelu2(fadd2_(xs2, xeg8), c, wsh, hf);   // row j=g+8, cols {tig,tig+4}
                // round-to-nearest tf32 of A (packed int add + mask)
                u64 h02 = (g02 + TF32_RND2) & TF32_MASK2;
                u64 h13 = (g13 + TF32_RND2) & TF32_MASK2;
                float h0, h2, h1, h3;
                unpack2(h02, h0, h2);
                unpack2(h13, h1, h3);
                uint32_t ah[4] = {__float_as_uint(h0), __float_as_uint(h1),
                                  __float_as_uint(h2), __float_as_uint(h3)};
                mma8(acc[mt][0], ah, bh0x, bh0y);
                mma8(acc[mt][0], ah, bl0x, bl0y);
                mma8(acc[mt][1], ah, bh1x, bh1y);
                mma8(acc[mt][1], ah, bl1x, bl1y);
            }
        }
    }

    // ---- epilogue: c0:(row g, n 2tig) c1:(row g, n 2tig+1) c2/c3: row g+8
#pragma unroll
    for (int mt = 0; mt < 2; mt++) {
        const int i = i0 + 2 * w + mt;
        float* r0 = out + ((size_t)(b * Lsz + i) * Lsz + (j0 + g)) * NL;
        float* r1 = out + ((size_t)(b * Lsz + i) * Lsz + (j0 + g + 8)) * NL;
#pragma unroll
        for (int nt = 0; nt < 2; nt++) {
            const int n = nt * 8 + 2 * tig;
            if (n < NL)     { r0[n]     = acc[mt][nt][0] + b2[n];
                              r1[n]     = acc[mt][nt][2] + b2[n]; }
            if (n + 1 < NL) { r0[n + 1] = acc[mt][nt][1] + b2[n + 1];
                              r1[n + 1] = acc[mt][nt][3] + b2[n + 1]; }
        }
    }
}

// ---------------------------------------------------------------------------
extern "C" void kernel_launch(void* const* d_in, const int* in_sizes, int n_in,
                              void* d_out, int out_size)
{
    const float* X  = (const float*)d_in[0];   // hidden_states (4,256,768)
    const float* W1 = (const float*)d_in[1];   // (1536,768)
    const float* b1 = (const float*)d_in[2];   // (768)
    const float* W2 = (const float*)d_in[3];   // (768,13)
    const float* b2 = (const float*)d_in[4];   // (13)
    float* out = (float*)d_out;                // (4,256,256,13)

    dim3 g1((2 * Hsz) / 64, (Bsz * Lsz) / 64);   // 24 x 16 = 384 blocks
    proj_kernel<<<g1, 256>>>(X, W1, b1);

    dim3 g2(Lsz / 16, Lsz / 16, Bsz);            // 16 x 16 x 4 = 1024 blocks
    span_kernel<<<g2, 256>>>(W2, b2, out);
}